// round 15
// baseline (speedup 1.0000x reference)
#include <cuda_runtime.h>
#include <math.h>

#define PI_C 3.14159f
#define TILE_PITCH 129                       // odd: vertical stride ≡ 1 mod 32
#define TILE_ROWS  129                       // +1 pad row (border replicate)
#define TILE_BYTES (TILE_ROWS * TILE_PITCH * 4)  // 66564

// ---------------- scratch (allocation-free rule: __device__ globals) --------
// mlp1 partial sums: [kc][b*256+j], kc in 0..3 (kc=0 includes bias b1)
__device__ float g_p1[4 * 8 * 256];
// transposed mlp2 weights: [f][d][k], f in {s, r, t0, t1}
__device__ float g_wT[4 * 256 * 256];

// ---------------- kernel 1: prep = mlp1 partials + weight transpose --------
__global__ void prep_kernel(const float* __restrict__ pc,
                            const float* __restrict__ W1,
                            const float* __restrict__ b1,
                            const float* __restrict__ Ws,
                            const float* __restrict__ Wr,
                            const float* __restrict__ Wt) {
    const int tid = threadIdx.x;
    const int bid = blockIdx.x;

    if (bid < 32) {
        // ---- mlp1 partial: 32 j-cols, 64-k slice, 8 batches in registers ----
        __shared__ float spc[8 * 64];
        __shared__ float part[8 * 8 * 32];
        const int jl = tid & 31;
        const int ks = tid >> 5;
        const int jc = bid & 7;
        const int kc = bid >> 3;
        const int j = jc * 32 + jl;
        const int kbase = kc * 64;

        #pragma unroll
        for (int i = tid; i < 512; i += 256)
            spc[i] = pc[(i >> 6) * 256 + kbase + (i & 63)];
        __syncthreads();

        float acc[8];
        #pragma unroll
        for (int b = 0; b < 8; ++b) acc[b] = 0.0f;

        #pragma unroll
        for (int kk = 0; kk < 8; ++kk) {
            const int kl = ks * 8 + kk;
            const float w = W1[(kbase + kl) * 256 + j];
            #pragma unroll
            for (int b = 0; b < 8; ++b) acc[b] = fmaf(spc[b * 64 + kl], w, acc[b]);
        }
        #pragma unroll
        for (int b = 0; b < 8; ++b) part[(ks * 8 + b) * 32 + jl] = acc[b];
        __syncthreads();

        const int jl2 = tid & 31;
        const int b2 = tid >> 5;
        float sum = (kc == 0) ? b1[jc * 32 + jl2] : 0.0f;
        #pragma unroll
        for (int k2 = 0; k2 < 8; ++k2) sum += part[(k2 * 8 + b2) * 32 + jl2];
        g_p1[kc * 2048 + b2 * 256 + jc * 32 + jl2] = sum;
    } else {
        // ---- weight transpose: g_wT[f][d][k] = W_f[k][d] ----
        __shared__ float t[32][33];
        const int tb = bid - 32;
        const int f = tb >> 6;                 // 4 families x 64 tiles
        const int t6 = tb & 63;
        const int d0 = (t6 & 7) * 32;
        const int k0 = (t6 >> 3) * 32;
        const int tx = tid & 31;
        const int ty = tid >> 5;               // 0..7

        #pragma unroll
        for (int jj = 0; jj < 4; ++jj) {
            const int k = k0 + ty + 8 * jj;
            const int d = d0 + tx;
            float v;
            if (f == 0)      v = Ws[k * 256 + d];
            else if (f == 1) v = Wr[k * 256 + d];
            else if (f == 2) v = Wt[k * 512 + 2 * d];
            else             v = Wt[k * 512 + 2 * d + 1];
            t[ty + 8 * jj][tx] = v;
        }
        __syncthreads();
        #pragma unroll
        for (int jj = 0; jj < 4; ++jj) {
            const int d = d0 + ty + 8 * jj;
            const int k = k0 + tx;
            g_wT[f * 65536 + d * 256 + k] = t[tx][ty + 8 * jj];
        }
    }
}

// ---------------- bilinear sample from padded, pitched tile -----------------
__device__ __forceinline__ float sample1(const float* __restrict__ tile,
                                         float px, float py) {
    px = fminf(fmaxf(px, 0.0f), 127.0f);    // border clamp
    py = fminf(fmaxf(py, 0.0f), 127.0f);
    const int ix = (int)px;                  // trunc == floor (px >= 0)
    const int iy = (int)py;
    const float wx = px - (float)ix;
    const float wy = py - (float)iy;
    const float* p = tile + iy * TILE_PITCH + ix;
    const float v00 = p[0];                  // pad makes +1 / +PITCH always safe
    const float v01 = p[1];
    const float v10 = p[TILE_PITCH];
    const float v11 = p[TILE_PITCH + 1];
    const float top = fmaf(wx, v01 - v00, v00);
    const float bot = fmaf(wx, v11 - v10, v10);
    return fmaf(wy, bot - top, top);
}

// ---------------- kernel 2: fused params + affine bilinear resample ---------
// grid: B*D = 2048 blocks, 512 threads, padded pitched tile (66564 B).
__global__ __launch_bounds__(512) void resample_kernel(
        const float* __restrict__ fm, float* __restrict__ out,
        const float* __restrict__ bs, const float* __restrict__ br,
        const float* __restrict__ bt) {
    extern __shared__ float tile[];           // 129 rows x 129 pitch
    __shared__ float s_raw[4];
    __shared__ float s_cf[6];                 // Ax, Ay, A0, Bx, By, B0
    const int n = blockIdx.x;                 // n = b*256 + d
    const int tid = threadIdx.x;
    const int b = n >> 8;
    const int d = n & 255;
    const float* __restrict__ img = fm + (size_t)n * 16384;

    // ---- stage-in: scalar lane-stride-1 (coalesced LDG, conflict-free STS) --
    #pragma unroll 8
    for (int i = tid; i < 16384; i += 512)
        tile[(i >> 7) * TILE_PITCH + (i & 127)] = img[i];
    // border-replicate pads (sourced from GMEM: no ordering dependency)
    if (tid < 129) {            // pad row 128 (incl corner at x=128)
        const int x = (tid < 128) ? tid : 127;
        tile[128 * TILE_PITCH + tid] = img[127 * 128 + x];
    } else if (tid < 257) {     // pad col 128 for rows 0..127
        const int y = tid - 129;
        tile[y * TILE_PITCH + 128] = img[y * 128 + 127];
    }

    // ---- param dot-products on warps 0-3 (one family each), overlapped ----
    if (tid < 128) {
        const int f = tid >> 5;               // family: s, r, t0, t1
        const int lane = tid & 31;
        const float* __restrict__ pp = g_p1 + b * 256;
        const float* __restrict__ wt = g_wT + f * 65536 + d * 256;

        float acc = 0.0f;
        #pragma unroll
        for (int i = 0; i < 8; ++i) {
            const int k = lane + 32 * i;      // lane-consecutive -> coalesced
            float pk = pp[k] + pp[2048 + k] + pp[2 * 2048 + k] + pp[3 * 2048 + k];
            pk = fmaxf(pk, 0.0f);             // relu(b1 + full k-sum)
            acc = fmaf(pk, wt[k], acc);
        }
        #pragma unroll
        for (int o = 16; o > 0; o >>= 1)
            acc += __shfl_xor_sync(0xFFFFFFFFu, acc, o);

        if (lane == 0) {
            float bias;
            if (f == 0)      bias = bs[d];
            else if (f == 1) bias = br[d];
            else if (f == 2) bias = bt[2 * d];
            else             bias = bt[2 * d + 1];
            s_raw[f] = acc + bias;
        }
    }
    __syncthreads();   // s_raw visible; stage-in + pads complete

    if (tid == 0) {
        const float scale = 2.0f / (1.0f + expf(-s_raw[0]));
        const float ang = tanhf(s_raw[1]) * PI_C;
        const float a = cosf(ang) * scale;
        const float s = sinf(ang) * scale;
        const float tx = tanhf(s_raw[2]);
        const float ty = tanhf(s_raw[3]);
        const float k64 = 64.0f * (2.0f / 127.0f);
        s_cf[0] = a * k64;                        // Ax
        s_cf[1] = -s * k64;                       // Ay
        s_cf[2] = (tx - a + s) * 64.0f + 63.5f;   // A0
        s_cf[3] = s * k64;                        // Bx
        s_cf[4] = a * k64;                        // By
        s_cf[5] = (ty - s - a) * 64.0f + 63.5f;   // B0
    }
    __syncthreads();

    const float Ax = s_cf[0], Ay = s_cf[1], A0 = s_cf[2];
    const float Bx = s_cf[3], By = s_cf[4], B0 = s_cf[5];

    // ---- sampling: 2 pixels/iter (rows y, y+64), incremental affine --------
    // x is lane-constant (stride 512 ≡ 0 mod 128): hoist the x terms.
    const float fx = (float)(tid & 127);
    const float fy0 = (float)(tid >> 7);          // 0..3
    float pxa = fmaf(Ay, fy0, fmaf(Ax, fx, A0));
    float pya = fmaf(By, fy0, fmaf(Bx, fx, B0));
    float pxb = fmaf(Ay, 64.0f, pxa);             // row y+64 twin
    float pyb = fmaf(By, 64.0f, pya);
    const float dAy = 4.0f * Ay;                  // y advances by 4 per iter
    const float dBy = 4.0f * By;

    float* __restrict__ o = out + (size_t)n * 16384;
    #pragma unroll 4
    for (int it = 0; it < 16; ++it) {
        const int ia = tid + (it << 9);
        o[ia]        = sample1(tile, pxa, pya);
        o[ia + 8192] = sample1(tile, pxb, pyb);
        pxa += dAy;  pya += dBy;
        pxb += dAy;  pyb += dBy;
    }
}

// ---------------- launch -----------------------------------------------------
extern "C" void kernel_launch(void* const* d_in, const int* in_sizes, int n_in,
                              void* d_out, int out_size) {
    const float* feature_map = (const float*)d_in[0];   // (8,256,128,128)
    const float* para_code   = (const float*)d_in[1];   // (8,256)
    const float* W1 = (const float*)d_in[2];            // (256,256)
    const float* b1 = (const float*)d_in[3];            // (256,)
    const float* Ws = (const float*)d_in[4];            // (256,256)
    const float* bs = (const float*)d_in[5];            // (256,)
    const float* Wr = (const float*)d_in[6];            // (256,256)
    const float* br = (const float*)d_in[7];            // (256,)
    const float* Wt = (const float*)d_in[8];            // (256,512)
    const float* bt = (const float*)d_in[9];            // (512,)
    float* out = (float*)d_out;

    cudaFuncSetAttribute(resample_kernel,
                         cudaFuncAttributeMaxDynamicSharedMemorySize, TILE_BYTES);

    prep_kernel<<<288, 256>>>(para_code, W1, b1, Ws, Wr, Wt);
    resample_kernel<<<2048, 512, TILE_BYTES>>>(feature_map, out, bs, br, bt);
}

// round 16
// speedup vs baseline: 1.2014x; 1.2014x over previous
#include <cuda_runtime.h>
#include <math.h>

#define PI_C 3.14159f
#define TILE_PITCH 129                       // odd: vertical stride ≡ 1 mod 32
#define TILE_ROWS  129                       // +1 pad row (border replicate)
#define TILE_BYTES (TILE_ROWS * TILE_PITCH * 4)  // 66564

// ---------------- scratch (allocation-free rule: __device__ globals) --------
// mlp1 partial sums: [kc][b*256+j], kc in 0..3 (kc=0 includes bias b1)
__device__ float g_p1[4 * 8 * 256];
// transposed mlp2 weights: [f][d][k], f in {s, r, t0, t1}
__device__ float g_wT[4 * 256 * 256];

// ---------------- kernel 1: prep = mlp1 partials + weight transpose --------
__global__ void prep_kernel(const float* __restrict__ pc,
                            const float* __restrict__ W1,
                            const float* __restrict__ b1,
                            const float* __restrict__ Ws,
                            const float* __restrict__ Wr,
                            const float* __restrict__ Wt) {
    const int tid = threadIdx.x;
    const int bid = blockIdx.x;

    if (bid < 32) {
        // ---- mlp1 partial: 32 j-cols, 64-k slice, 8 batches in registers ----
        __shared__ float spc[8 * 64];
        __shared__ float part[8 * 8 * 32];
        const int jl = tid & 31;
        const int ks = tid >> 5;
        const int jc = bid & 7;
        const int kc = bid >> 3;
        const int j = jc * 32 + jl;
        const int kbase = kc * 64;

        #pragma unroll
        for (int i = tid; i < 512; i += 256)
            spc[i] = pc[(i >> 6) * 256 + kbase + (i & 63)];
        __syncthreads();

        float acc[8];
        #pragma unroll
        for (int b = 0; b < 8; ++b) acc[b] = 0.0f;

        #pragma unroll
        for (int kk = 0; kk < 8; ++kk) {
            const int kl = ks * 8 + kk;
            const float w = W1[(kbase + kl) * 256 + j];
            #pragma unroll
            for (int b = 0; b < 8; ++b) acc[b] = fmaf(spc[b * 64 + kl], w, acc[b]);
        }
        #pragma unroll
        for (int b = 0; b < 8; ++b) part[(ks * 8 + b) * 32 + jl] = acc[b];
        __syncthreads();

        const int jl2 = tid & 31;
        const int b2 = tid >> 5;
        float sum = (kc == 0) ? b1[jc * 32 + jl2] : 0.0f;
        #pragma unroll
        for (int k2 = 0; k2 < 8; ++k2) sum += part[(k2 * 8 + b2) * 32 + jl2];
        g_p1[kc * 2048 + b2 * 256 + jc * 32 + jl2] = sum;
    } else {
        // ---- weight transpose: g_wT[f][d][k] = W_f[k][d] ----
        __shared__ float t[32][33];
        const int tb = bid - 32;
        const int f = tb >> 6;                 // 4 families x 64 tiles
        const int t6 = tb & 63;
        const int d0 = (t6 & 7) * 32;
        const int k0 = (t6 >> 3) * 32;
        const int tx = tid & 31;
        const int ty = tid >> 5;               // 0..7

        #pragma unroll
        for (int jj = 0; jj < 4; ++jj) {
            const int k = k0 + ty + 8 * jj;
            const int d = d0 + tx;
            float v;
            if (f == 0)      v = Ws[k * 256 + d];
            else if (f == 1) v = Wr[k * 256 + d];
            else if (f == 2) v = Wt[k * 512 + 2 * d];
            else             v = Wt[k * 512 + 2 * d + 1];
            t[ty + 8 * jj][tx] = v;
        }
        __syncthreads();
        #pragma unroll
        for (int jj = 0; jj < 4; ++jj) {
            const int d = d0 + ty + 8 * jj;
            const int k = k0 + tx;
            g_wT[f * 65536 + d * 256 + k] = t[tx][ty + 8 * jj];
        }
    }
}

// ---------------- bilinear sample from padded, pitched tile -----------------
__device__ __forceinline__ float sample1(const float* __restrict__ tile,
                                         float px, float py) {
    px = fminf(fmaxf(px, 0.0f), 127.0f);    // border clamp
    py = fminf(fmaxf(py, 0.0f), 127.0f);
    const int ix = (int)px;                  // trunc == floor (px >= 0)
    const int iy = (int)py;
    const float wx = px - (float)ix;
    const float wy = py - (float)iy;
    const float* p = tile + iy * TILE_PITCH + ix;
    const float v00 = p[0];                  // pad makes +1 / +PITCH always safe
    const float v01 = p[1];
    const float v10 = p[TILE_PITCH];
    const float v11 = p[TILE_PITCH + 1];
    const float top = fmaf(wx, v01 - v00, v00);
    const float bot = fmaf(wx, v11 - v10, v10);
    return fmaf(wy, bot - top, top);
}

// ---------------- kernel 2: fused params + affine bilinear resample ---------
// grid: B*D = 2048 blocks, 512 threads, padded pitched tile (66564 B).
__global__ __launch_bounds__(512) void resample_kernel(
        const float* __restrict__ fm, float* __restrict__ out,
        const float* __restrict__ bs, const float* __restrict__ br,
        const float* __restrict__ bt) {
    extern __shared__ float tile[];           // 129 rows x 129 pitch
    __shared__ float s_raw[4];
    __shared__ float s_cf[6];                 // Ax, Ay, A0, Bx, By, B0
    const int n = blockIdx.x;                 // n = b*256 + d
    const int tid = threadIdx.x;
    const int b = n >> 8;
    const int d = n & 255;
    const float* __restrict__ img = fm + (size_t)n * 16384;

    // ---- stage-in: scalar lane-stride-1 (coalesced LDG, conflict-free STS) --
    #pragma unroll 8
    for (int i = tid; i < 16384; i += 512)
        tile[(i >> 7) * TILE_PITCH + (i & 127)] = img[i];
    // border-replicate pads (sourced from GMEM: no ordering dependency)
    if (tid < 129) {            // pad row 128 (incl corner at x=128)
        const int x = (tid < 128) ? tid : 127;
        tile[128 * TILE_PITCH + tid] = img[127 * 128 + x];
    } else if (tid < 257) {     // pad col 128 for rows 0..127
        const int y = tid - 129;
        tile[y * TILE_PITCH + 128] = img[y * 128 + 127];
    }

    // ---- param dot-products on warps 0-3 (one family each), overlapped ----
    if (tid < 128) {
        const int f = tid >> 5;               // family: s, r, t0, t1
        const int lane = tid & 31;
        const float* __restrict__ pp = g_p1 + b * 256;
        const float* __restrict__ wt = g_wT + f * 65536 + d * 256;

        float acc = 0.0f;
        #pragma unroll
        for (int i = 0; i < 8; ++i) {
            const int k = lane + 32 * i;      // lane-consecutive -> coalesced
            float pk = pp[k] + pp[2048 + k] + pp[2 * 2048 + k] + pp[3 * 2048 + k];
            pk = fmaxf(pk, 0.0f);             // relu(b1 + full k-sum)
            acc = fmaf(pk, wt[k], acc);
        }
        #pragma unroll
        for (int o = 16; o > 0; o >>= 1)
            acc += __shfl_xor_sync(0xFFFFFFFFu, acc, o);

        if (lane == 0) {
            float bias;
            if (f == 0)      bias = bs[d];
            else if (f == 1) bias = br[d];
            else if (f == 2) bias = bt[2 * d];
            else             bias = bt[2 * d + 1];
            s_raw[f] = acc + bias;
        }
    }
    __syncthreads();   // s_raw visible; stage-in + pads complete

    if (tid == 0) {
        const float scale = 2.0f / (1.0f + expf(-s_raw[0]));
        const float ang = tanhf(s_raw[1]) * PI_C;
        const float a = cosf(ang) * scale;
        const float s = sinf(ang) * scale;
        const float tx = tanhf(s_raw[2]);
        const float ty = tanhf(s_raw[3]);
        const float k64 = 64.0f * (2.0f / 127.0f);
        s_cf[0] = a * k64;                        // Ax
        s_cf[1] = -s * k64;                       // Ay
        s_cf[2] = (tx - a + s) * 64.0f + 63.5f;   // A0
        s_cf[3] = s * k64;                        // Bx
        s_cf[4] = a * k64;                        // By
        s_cf[5] = (ty - s - a) * 64.0f + 63.5f;   // B0
    }
    __syncthreads();

    const float Ax = s_cf[0], Ay = s_cf[1], A0 = s_cf[2];
    const float Bx = s_cf[3], By = s_cf[4], B0 = s_cf[5];

    // ---- sampling: 2 rows/iter (y, y+64), coordinates INDEPENDENT per iter --
    // x is lane-constant (stride 512 ≡ 0 mod 128): hoist the x terms once.
    const float fx = (float)(tid & 127);
    const float fy0 = (float)(tid >> 7);          // 0..3
    const float bx = fmaf(Ax, fx, A0);            // x-contribution to px
    const float by = fmaf(Bx, fx, B0);            // x-contribution to py

    float* __restrict__ o = out + (size_t)n * 16384;
    #pragma unroll 4
    for (int it = 0; it < 16; ++it) {
        const float ya = fy0 + (float)(4 * it);   // compile-time per body
        const float yb = ya + 64.0f;
        // independent FMAs from loop-invariants: full MLP across unroll
        const float pxa = fmaf(Ay, ya, bx);
        const float pya = fmaf(By, ya, by);
        const float pxb = fmaf(Ay, yb, bx);
        const float pyb = fmaf(By, yb, by);
        const int ia = tid + (it << 9);
        o[ia]        = sample1(tile, pxa, pya);
        o[ia + 8192] = sample1(tile, pxb, pyb);
    }
}

// ---------------- launch -----------------------------------------------------
extern "C" void kernel_launch(void* const* d_in, const int* in_sizes, int n_in,
                              void* d_out, int out_size) {
    const float* feature_map = (const float*)d_in[0];   // (8,256,128,128)
    const float* para_code   = (const float*)d_in[1];   // (8,256)
    const float* W1 = (const float*)d_in[2];            // (256,256)
    const float* b1 = (const float*)d_in[3];            // (256,)
    const float* Ws = (const float*)d_in[4];            // (256,256)
    const float* bs = (const float*)d_in[5];            // (256,)
    const float* Wr = (const float*)d_in[6];            // (256,256)
    const float* br = (const float*)d_in[7];            // (256,)
    const float* Wt = (const float*)d_in[8];            // (256,512)
    const float* bt = (const float*)d_in[9];            // (512,)
    float* out = (float*)d_out;

    cudaFuncSetAttribute(resample_kernel,
                         cudaFuncAttributeMaxDynamicSharedMemorySize, TILE_BYTES);

    prep_kernel<<<288, 256>>>(para_code, W1, b1, Ws, Wr, Wt);
    resample_kernel<<<2048, 512, TILE_BYTES>>>(feature_map, out, bs, br, bt);
}

// round 17
// speedup vs baseline: 1.2247x; 1.0194x over previous
#include <cuda_runtime.h>
#include <cuda_fp16.h>
#include <math.h>

#define PI_C 3.14159f
#define TILE_PITCH 129                       // odd: vertical stride ≡ 1 mod 32
#define TILE_BYTES (129 * TILE_PITCH * 4)    // 129 rows (incl pad) x 129 half2

// ---------------- scratch (allocation-free rule: __device__ globals) --------
__device__ float g_p1[4 * 8 * 256];   // mlp1 partials [kc][b*256+j]
__device__ float g_wT[4 * 256 * 256]; // transposed mlp2 weights [f][d][k]

// ---------------- kernel 1: prep = mlp1 partials + weight transpose --------
__global__ void prep_kernel(const float* __restrict__ pc,
                            const float* __restrict__ W1,
                            const float* __restrict__ b1,
                            const float* __restrict__ Ws,
                            const float* __restrict__ Wr,
                            const float* __restrict__ Wt) {
    const int tid = threadIdx.x;
    const int bid = blockIdx.x;

    if (bid < 32) {
        __shared__ float spc[8 * 64];
        __shared__ float part[8 * 8 * 32];
        const int jl = tid & 31;
        const int ks = tid >> 5;
        const int jc = bid & 7;
        const int kc = bid >> 3;
        const int j = jc * 32 + jl;
        const int kbase = kc * 64;

        #pragma unroll
        for (int i = tid; i < 512; i += 256)
            spc[i] = pc[(i >> 6) * 256 + kbase + (i & 63)];
        __syncthreads();

        float acc[8];
        #pragma unroll
        for (int b = 0; b < 8; ++b) acc[b] = 0.0f;

        #pragma unroll
        for (int kk = 0; kk < 8; ++kk) {
            const int kl = ks * 8 + kk;
            const float w = W1[(kbase + kl) * 256 + j];
            #pragma unroll
            for (int b = 0; b < 8; ++b) acc[b] = fmaf(spc[b * 64 + kl], w, acc[b]);
        }
        #pragma unroll
        for (int b = 0; b < 8; ++b) part[(ks * 8 + b) * 32 + jl] = acc[b];
        __syncthreads();

        const int jl2 = tid & 31;
        const int b2 = tid >> 5;
        float sum = (kc == 0) ? b1[jc * 32 + jl2] : 0.0f;
        #pragma unroll
        for (int k2 = 0; k2 < 8; ++k2) sum += part[(k2 * 8 + b2) * 32 + jl2];
        g_p1[kc * 2048 + b2 * 256 + jc * 32 + jl2] = sum;
    } else {
        __shared__ float t[32][33];
        const int tb = bid - 32;
        const int f = tb >> 6;
        const int t6 = tb & 63;
        const int d0 = (t6 & 7) * 32;
        const int k0 = (t6 >> 3) * 32;
        const int tx = tid & 31;
        const int ty = tid >> 5;

        #pragma unroll
        for (int jj = 0; jj < 4; ++jj) {
            const int k = k0 + ty + 8 * jj;
            const int d = d0 + tx;
            float v;
            if (f == 0)      v = Ws[k * 256 + d];
            else if (f == 1) v = Wr[k * 256 + d];
            else if (f == 2) v = Wt[k * 512 + 2 * d];
            else             v = Wt[k * 512 + 2 * d + 1];
            t[ty + 8 * jj][tx] = v;
        }
        __syncthreads();
        #pragma unroll
        for (int jj = 0; jj < 4; ++jj) {
            const int d = d0 + ty + 8 * jj;
            const int k = k0 + tx;
            g_wT[f * 65536 + d * 256 + k] = t[tx][ty + 8 * jj];
        }
    }
}

// ---------------- bilinear sample: half2 texel-pair tile, 2 LDS/pixel -------
__device__ __forceinline__ float sample1(const __half2* __restrict__ tile2,
                                         float px, float py) {
    px = fminf(fmaxf(px, 0.0f), 127.0f);    // border clamp
    py = fminf(fmaxf(py, 0.0f), 127.0f);
    const float fx = floorf(px);
    const float fy = floorf(py);
    const float wx = px - fx;
    const float wy = py - fy;
    const __half2* p = tile2 + (int)fy * TILE_PITCH + (int)fx;
    const float2 lo = __half22float2(p[0]);          // (v00, v01)
    const float2 hi = __half22float2(p[TILE_PITCH]); // (v10, v11) pad row safe
    const float top = fmaf(wx, lo.y - lo.x, lo.x);
    const float bot = fmaf(wx, hi.y - hi.x, hi.x);
    return fmaf(wy, bot - top, top);
}

// ---------------- kernel 2: fused params + affine bilinear resample ---------
// grid: B*D = 2048 blocks, 512 threads, half2-pair pitched tile (66564 B).
__global__ __launch_bounds__(512) void resample_kernel(
        const float* __restrict__ fm, float* __restrict__ out,
        const float* __restrict__ bs, const float* __restrict__ br,
        const float* __restrict__ bt) {
    extern __shared__ __half2 tile2[];        // 129 rows x 129 pitch (half2)
    __shared__ float s_raw[4];
    __shared__ float s_cf[6];                 // Ax, Ay, A0, Bx, By, B0
    const int n = blockIdx.x;                 // n = b*256 + d
    const int tid = threadIdx.x;
    const int b = n >> 8;
    const int d = n & 255;
    const float* __restrict__ img = fm + (size_t)n * 16384;

    // ---- stage-in: build (v[x], v[x+1]) half2 pairs, lane-stride-1 STS -----
    #pragma unroll 8
    for (int i = tid; i < 16384; i += 512) {
        const int x = i & 127;
        const float v0 = img[i];
        const float v1 = img[i + (x < 127 ? 1 : 0)];   // L1-hit neighbor
        tile2[(i >> 7) * TILE_PITCH + x] = __floats2half2_rn(v0, v1);
    }
    if (tid < 128) {   // pad row 128 = replicate row 127 pairs
        const float v0 = img[127 * 128 + tid];
        const float v1 = img[127 * 128 + (tid < 127 ? tid + 1 : tid)];
        tile2[128 * TILE_PITCH + tid] = __floats2half2_rn(v0, v1);
    }

    // ---- param dot-products on warps 0-3 (one family each), overlapped ----
    if (tid < 128) {
        const int f = tid >> 5;
        const int lane = tid & 31;
        const float* __restrict__ pp = g_p1 + b * 256;
        const float* __restrict__ wt = g_wT + f * 65536 + d * 256;

        float acc = 0.0f;
        #pragma unroll
        for (int i = 0; i < 8; ++i) {
            const int k = lane + 32 * i;
            float pk = pp[k] + pp[2048 + k] + pp[2 * 2048 + k] + pp[3 * 2048 + k];
            pk = fmaxf(pk, 0.0f);
            acc = fmaf(pk, wt[k], acc);
        }
        #pragma unroll
        for (int o = 16; o > 0; o >>= 1)
            acc += __shfl_xor_sync(0xFFFFFFFFu, acc, o);

        if (lane == 0) {
            float bias;
            if (f == 0)      bias = bs[d];
            else if (f == 1) bias = br[d];
            else if (f == 2) bias = bt[2 * d];
            else             bias = bt[2 * d + 1];
            s_raw[f] = acc + bias;
        }
    }
    __syncthreads();

    if (tid == 0) {
        const float scale = 2.0f / (1.0f + expf(-s_raw[0]));
        const float ang = tanhf(s_raw[1]) * PI_C;
        const float a = cosf(ang) * scale;
        const float s = sinf(ang) * scale;
        const float tx = tanhf(s_raw[2]);
        const float ty = tanhf(s_raw[3]);
        const float k64 = 64.0f * (2.0f / 127.0f);
        s_cf[0] = a * k64;                        // Ax
        s_cf[1] = -s * k64;                       // Ay
        s_cf[2] = (tx - a + s) * 64.0f + 63.5f;   // A0
        s_cf[3] = s * k64;                        // Bx
        s_cf[4] = a * k64;                        // By
        s_cf[5] = (ty - s - a) * 64.0f + 63.5f;   // B0
    }
    __syncthreads();

    const float Ax = s_cf[0], Ay = s_cf[1], A0 = s_cf[2];
    const float Bx = s_cf[3], By = s_cf[4], B0 = s_cf[5];

    // ---- sampling: 4 independent rows/iter (y, +32, +64, +96), 8 iters -----
    // x is lane-constant: hoist its terms. Coordinates are independent FMAs
    // from loop-invariants each body (no loop-carried FP chain -> full MLP).
    const float fx = (float)(tid & 127);
    const float fy0 = (float)(tid >> 7);          // 0..3
    const float bx = fmaf(Ax, fx, A0);
    const float by = fmaf(Bx, fx, B0);

    float* __restrict__ o = out + (size_t)n * 16384;
    #pragma unroll 2
    for (int it = 0; it < 8; ++it) {
        const float ya = fy0 + (float)(4 * it);
        const int ia = tid + (it << 9);
        #pragma unroll
        for (int c = 0; c < 4; ++c) {            // rows ya + 32c
            const float y = ya + (float)(32 * c);
            const float px = fmaf(Ay, y, bx);
            const float py = fmaf(By, y, by);
            o[ia + 4096 * c] = sample1(tile2, px, py);
        }
    }
}

// ---------------- launch -----------------------------------------------------
extern "C" void kernel_launch(void* const* d_in, const int* in_sizes, int n_in,
                              void* d_out, int out_size) {
    const float* feature_map = (const float*)d_in[0];   // (8,256,128,128)
    const float* para_code   = (const float*)d_in[1];   // (8,256)
    const float* W1 = (const float*)d_in[2];            // (256,256)
    const float* b1 = (const float*)d_in[3];            // (256,)
    const float* Ws = (const float*)d_in[4];            // (256,256)
    const float* bs = (const float*)d_in[5];            // (256,)
    const float* Wr = (const float*)d_in[6];            // (256,256)
    const float* br = (const float*)d_in[7];            // (256,)
    const float* Wt = (const float*)d_in[8];            // (256,512)
    const float* bt = (const float*)d_in[9];            // (512,)
    float* out = (float*)d_out;

    cudaFuncSetAttribute(resample_kernel,
                         cudaFuncAttributeMaxDynamicSharedMemorySize, TILE_BYTES);

    prep_kernel<<<288, 256>>>(para_code, W1, b1, Ws, Wr, Wt);
    resample_kernel<<<2048, 512, TILE_BYTES>>>(feature_map, out, bs, br, bt);
}